// round 11
// baseline (speedup 1.0000x reference)
#include <cuda_runtime.h>
#include <cuda_fp16.h>
#include <math.h>
#include <stdint.h>

// ---------------- problem constants ----------------
#define N_NODES 50000
#define NUM_FEA 213
#define HID1 16
#define HEAD1 12
#define CH1 (HID1*HEAD1)   // 192
#define HID2 8
#define HEAD2 8
#define CH2 (HID2*HEAD2)   // 64
#define E_EDGES 800000
#define E_TOT (E_EDGES + N_NODES)

// ---------------- device scratch ----------------
static __device__ float  g_h1[N_NODES*CH1];
static __device__ __half g_h1h[N_NODES*CH1];
static __device__ float  g_x1[N_NODES*CH1];
static __device__ float  g_h2[N_NODES*CH2];
static __device__ __half g_h2h[N_NODES*CH2];
static __device__ float  g_as1[N_NODES*HEAD1];
static __device__ float  g_ad1[N_NODES*HEAD1];
static __device__ float  g_as2[N_NODES*HEAD2];
static __device__ float  g_ad2[N_NODES*HEAD2];
static __device__ int    g_deg[N_NODES];
static __device__ int    g_cur[N_NODES];
static __device__ int    g_tmp[N_NODES];
static __device__ int    g_offs[N_NODES+1];
static __device__ int    g_bsum[64];
static __device__ int    g_srcs[E_TOT];

// ---------------- CSR build ----------------
__global__ void zero_kernel(int n)
{
    int i = blockIdx.x*blockDim.x + threadIdx.x;
    if (i < n) { g_deg[i] = 0; g_cur[i] = 0; }
}

__global__ void count_kernel(const int* __restrict__ dstE, int E, int n)
{
    int i = blockIdx.x*blockDim.x + threadIdx.x;
    int tot = E + n;
    if (i >= tot) return;
    int d = (i < E) ? dstE[i] : (i - E);
    atomicAdd(&g_deg[d], 1);
}

__global__ void scan1_kernel(int n)
{
    __shared__ int sh[1024];
    int t = threadIdx.x;
    int i = blockIdx.x*1024 + t;
    sh[t] = (i < n) ? g_deg[i] : 0;
    __syncthreads();
    #pragma unroll
    for (int off = 1; off < 1024; off <<= 1) {
        int v = 0;
        if (t >= off) v = sh[t-off];
        __syncthreads();
        sh[t] += v;
        __syncthreads();
    }
    if (i < n) g_tmp[i] = sh[t];
    if (t == 1023) g_bsum[blockIdx.x] = sh[1023];
}

__global__ void scan2_kernel(int nb)
{
    __shared__ int sh[64];
    int t = threadIdx.x;
    int mine = (t < nb) ? g_bsum[t] : 0;
    sh[t] = mine;
    __syncthreads();
    #pragma unroll
    for (int off = 1; off < 64; off <<= 1) {
        int v = (t >= off) ? sh[t-off] : 0;
        __syncthreads();
        sh[t] += v;
        __syncthreads();
    }
    if (t < nb) g_bsum[t] = sh[t] - mine;
}

__global__ void scan3_kernel(int n)
{
    int i = blockIdx.x*blockDim.x + threadIdx.x;
    if (i < n) g_offs[i+1] = g_tmp[i] + g_bsum[i >> 10];
    if (i == 0) g_offs[0] = 0;
}

__global__ void scatter_kernel(const int* __restrict__ srcE,
                               const int* __restrict__ dstE, int E, int n)
{
    int i = blockIdx.x*blockDim.x + threadIdx.x;
    int tot = E + n;
    if (i >= tot) return;
    int s, d;
    if (i < E) { s = srcE[i]; d = dstE[i]; }
    else       { s = d = i - E; }
    int pos = g_offs[d] + atomicAdd(&g_cur[d], 1);
    g_srcs[pos] = s;
}

// ---------------- 3x-bf16 tensor-core GEMM (m16n8k16), double-buffered -----
__device__ __forceinline__ uint32_t pack2(float v0, float v1)
{
    uint32_t d;
    asm("cvt.rn.bf16x2.f32 %0, %1, %2;" : "=r"(d) : "f"(v1), "f"(v0));
    return d;
}
__device__ __forceinline__ float lo_f(uint32_t d) { return __uint_as_float(d << 16); }
__device__ __forceinline__ float hi_f(uint32_t d) { return __uint_as_float(d & 0xffff0000u); }

__device__ __forceinline__ void mma_bf16(float* d, const uint32_t* a, const uint32_t* b)
{
    asm volatile("mma.sync.aligned.m16n8k16.row.col.f32.bf16.bf16.f32 "
                 "{%0,%1,%2,%3}, {%4,%5,%6,%7}, {%8,%9}, {%0,%1,%2,%3};"
                 : "+f"(d[0]), "+f"(d[1]), "+f"(d[2]), "+f"(d[3])
                 : "r"(a[0]), "r"(a[1]), "r"(a[2]), "r"(a[3]),
                   "r"(b[0]), "r"(b[1]));
}

// Writes fp32 C and an fp16 copy C16 (for the aggregation gather).
template<int BN>
__global__ __launch_bounds__(256, 2)
void gemm_tc_kernel(const float* __restrict__ A,
                    const float* __restrict__ B,
                    float* __restrict__ C,
                    __half* __restrict__ C16,
                    int M, int N, int K)
{
    constexpr int BM = 128, BK = 16;
    constexpr int BNp = BN + 2;
    constexpr int WN = BN/2;
    constexpr int NT = WN/8;
    constexpr int NBS = (4*BN + 255)/256;
    constexpr int ASZ = 8*2*32*4;
    constexpr int BSZ = 4*BNp*4;

    __shared__ uint32_t sA[2][ASZ];
    __shared__ uint32_t sB[2][BSZ];

    const int tx   = threadIdx.x;
    const int lane = tx & 31;
    const int wid  = tx >> 5;
    const int wm   = wid & 3;
    const int wc   = wid >> 2;

    const int row0 = blockIdx.x * BM;
    const int col0 = blockIdx.y * BN;

    const int sg  = tx >> 5;
    const int srr = lane >> 2;
    const int scc = lane & 3;

    const int r0g = row0 + sg*16 + srr;
    const int r1g = r0g + 8;
    const bool r0ok = r0g < M, r1ok = r1g < M;
    const long r0a = (long)(r0ok ? r0g : 0) * K;
    const long r1a = (long)(r1ok ? r1g : 0) * K;

    float av[2][4];
    float bv[NBS][4];

    float acc[2][NT][4];
    #pragma unroll
    for (int gi = 0; gi < 2; gi++)
        #pragma unroll
        for (int nt = 0; nt < NT; nt++)
            #pragma unroll
            for (int j = 0; j < 4; j++) acc[gi][nt][j] = 0.f;

    const int nk = (K + BK - 1) / BK;

    auto load_regs = [&](int kt) {
        const int k0 = kt * BK;
        #pragma unroll
        for (int p = 0; p < 2; p++) {
            int kq = k0 + 2*scc + 8*p;
            bool k0ok = kq < K, k1ok = (kq+1) < K;
            av[p][0] = (r0ok && k0ok) ? A[r0a + kq]     : 0.f;
            av[p][1] = (r0ok && k1ok) ? A[r0a + kq + 1] : 0.f;
            av[p][2] = (r1ok && k0ok) ? A[r1a + kq]     : 0.f;
            av[p][3] = (r1ok && k1ok) ? A[r1a + kq + 1] : 0.f;
        }
        #pragma unroll
        for (int i = 0; i < NBS; i++) {
            int s = tx + i*256;
            if (s < 4*BN) {
                int tg = s / BN, c = s - tg*BN;
                int k = k0 + 2*tg;
                bv[i][0] = (k   < K) ? B[(long)k*N     + col0 + c] : 0.f;
                bv[i][1] = (k+1 < K) ? B[(long)(k+1)*N + col0 + c] : 0.f;
                bv[i][2] = (k+8 < K) ? B[(long)(k+8)*N + col0 + c] : 0.f;
                bv[i][3] = (k+9 < K) ? B[(long)(k+9)*N + col0 + c] : 0.f;
            }
        }
    };

    auto cvt_sts = [&](int buf) {
        uint32_t ahi[4], alo[4];
        ahi[0] = pack2(av[0][0], av[0][1]);
        ahi[1] = pack2(av[0][2], av[0][3]);
        ahi[2] = pack2(av[1][0], av[1][1]);
        ahi[3] = pack2(av[1][2], av[1][3]);
        alo[0] = pack2(av[0][0] - lo_f(ahi[0]), av[0][1] - hi_f(ahi[0]));
        alo[1] = pack2(av[0][2] - lo_f(ahi[1]), av[0][3] - hi_f(ahi[1]));
        alo[2] = pack2(av[1][0] - lo_f(ahi[2]), av[1][1] - hi_f(ahi[2]));
        alo[3] = pack2(av[1][2] - lo_f(ahi[3]), av[1][3] - hi_f(ahi[3]));
        *(uint4*)&sA[buf][((sg*2 + 0)*32 + lane)*4] = make_uint4(ahi[0],ahi[1],ahi[2],ahi[3]);
        *(uint4*)&sA[buf][((sg*2 + 1)*32 + lane)*4] = make_uint4(alo[0],alo[1],alo[2],alo[3]);
        #pragma unroll
        for (int i = 0; i < NBS; i++) {
            int s = tx + i*256;
            if (s < 4*BN) {
                int tg = s / BN, c = s - tg*BN;
                uint32_t bh0 = pack2(bv[i][0], bv[i][1]);
                uint32_t bh1 = pack2(bv[i][2], bv[i][3]);
                uint32_t bl0 = pack2(bv[i][0] - lo_f(bh0), bv[i][1] - hi_f(bh0));
                uint32_t bl1 = pack2(bv[i][2] - lo_f(bh1), bv[i][3] - hi_f(bh1));
                *(uint4*)&sB[buf][(tg*BNp + c)*4] = make_uint4(bh0, bh1, bl0, bl1);
            }
        }
    };

    auto compute = [&](int buf) {
        uint32_t ahi[2][4], alo[2][4];
        #pragma unroll
        for (int gi = 0; gi < 2; gi++) {
            int g = wm*2 + gi;
            uint4 h = *(const uint4*)&sA[buf][((g*2 + 0)*32 + lane)*4];
            uint4 l = *(const uint4*)&sA[buf][((g*2 + 1)*32 + lane)*4];
            ahi[gi][0]=h.x; ahi[gi][1]=h.y; ahi[gi][2]=h.z; ahi[gi][3]=h.w;
            alo[gi][0]=l.x; alo[gi][1]=l.y; alo[gi][2]=l.z; alo[gi][3]=l.w;
        }
        #pragma unroll
        for (int nt = 0; nt < NT; nt++) {
            int nc = wc*WN + nt*8 + (lane >> 2);
            uint4 b4 = *(const uint4*)&sB[buf][((lane & 3)*BNp + nc)*4];
            uint32_t bhi[2] = {b4.x, b4.y};
            uint32_t blo[2] = {b4.z, b4.w};
            #pragma unroll
            for (int gi = 0; gi < 2; gi++) {
                mma_bf16(acc[gi][nt], ahi[gi], bhi);
                mma_bf16(acc[gi][nt], ahi[gi], blo);
                mma_bf16(acc[gi][nt], alo[gi], bhi);
            }
        }
    };

    load_regs(0);
    cvt_sts(0);
    if (nk > 1) load_regs(1);
    __syncthreads();

    for (int kt = 0; kt < nk; kt++) {
        compute(kt & 1);
        if (kt + 1 < nk) {
            cvt_sts((kt + 1) & 1);
            __syncthreads();
            if (kt + 2 < nk) load_regs(kt + 2);
        }
    }

    #pragma unroll
    for (int gi = 0; gi < 2; gi++) {
        int gr0 = row0 + (wm*2 + gi)*16 + (lane >> 2);
        int gr1 = gr0 + 8;
        #pragma unroll
        for (int nt = 0; nt < NT; nt++) {
            int gc = col0 + wc*WN + nt*8 + (lane & 3)*2;
            if (gr0 < M) {
                *(float2*)&C[(long)gr0*N + gc] = make_float2(acc[gi][nt][0], acc[gi][nt][1]);
                *(__half2*)&C16[(long)gr0*N + gc] = __floats2half2_rn(acc[gi][nt][0], acc[gi][nt][1]);
            }
            if (gr1 < M) {
                *(float2*)&C[(long)gr1*N + gc] = make_float2(acc[gi][nt][2], acc[gi][nt][3]);
                *(__half2*)&C16[(long)gr1*N + gc] = __floats2half2_rn(acc[gi][nt][2], acc[gi][nt][3]);
            }
        }
    }
}

// ---------------- attention scores (fp32 h) ----------------
template<int H, int C>
__global__ void attn_kernel(const float* __restrict__ h,
                            const float* __restrict__ att_s,
                            const float* __restrict__ att_d,
                            float* __restrict__ as_out,
                            float* __restrict__ ad_out, int N)
{
    int t = blockIdx.x*blockDim.x + threadIdx.x;
    if (t >= N*H) return;
    int hh = t % H;
    const float* hp = h + (long)t * C;
    const float* sp = att_s + hh*C;
    const float* dp = att_d + hh*C;
    float s = 0.f, d = 0.f;
    #pragma unroll
    for (int c = 0; c < C; c += 4) {
        float4 hv = *(const float4*)&hp[c];
        float4 sv = *(const float4*)&sp[c];
        float4 dv = *(const float4*)&dp[c];
        s = fmaf(hv.x,sv.x, fmaf(hv.y,sv.y, fmaf(hv.z,sv.z, fmaf(hv.w,sv.w, s))));
        d = fmaf(hv.x,dv.x, fmaf(hv.y,dv.y, fmaf(hv.z,dv.z, fmaf(hv.w,dv.w, d))));
    }
    as_out[t] = s;
    ad_out[t] = d;
}

// ---------------- per-dst softmax aggregation, fp16 h gather, 2-edge unroll -
// All arithmetic fp32; h[src] gathered as fp16 (halves L2 line traffic).
template<int H, int C>
__global__ void agg_kernel(const __half* __restrict__ h,
                           const float* __restrict__ as_in,
                           const float* __restrict__ ad_in,
                           const float* __restrict__ bias,
                           float* __restrict__ out, int N)
{
    constexpr int CH = H*C;
    constexpr int NFULL = CH/128;
    constexpr bool HASREM = (CH % 128) != 0;
    int warp = (blockIdx.x*blockDim.x + threadIdx.x) >> 5;
    int lane = threadIdx.x & 31;
    if (warp >= N) return;
    const int v = warp;

    float adv = (lane < H) ? ad_in[v*H + lane] : 0.f;
    int b = g_offs[v], e = g_offs[v+1];

    int headF[NFULL > 0 ? NFULL : 1];
    #pragma unroll
    for (int j = 0; j < NFULL; j++) headF[j] = (j*128 + 4*lane) / C;
    const int headR = (NFULL*128 + 2*lane) / C;

    float den = 0.f;
    float4 accF[NFULL > 0 ? NFULL : 1];
    #pragma unroll
    for (int j = 0; j < NFULL; j++) accF[j] = make_float4(0.f,0.f,0.f,0.f);
    float2 accR = make_float2(0.f, 0.f);

    int i = b;
    for (; i + 1 < e; i += 2) {
        int s0 = g_srcs[i];
        int s1 = g_srcs[i+1];
        float ev0 = 0.f, ev1 = 0.f;
        if (lane < H) {
            ev0 = as_in[s0*H + lane];
            ev1 = as_in[s1*H + lane];
        }
        const __half* hp0 = h + (long)s0*CH;
        const __half* hp1 = h + (long)s1*CH;
        uint2 rv0[NFULL > 0 ? NFULL : 1], rv1[NFULL > 0 ? NFULL : 1];
        uint32_t rr0 = 0, rr1 = 0;
        #pragma unroll
        for (int j = 0; j < NFULL; j++) {
            rv0[j] = *(const uint2*)(hp0 + j*128 + 4*lane);
            rv1[j] = *(const uint2*)(hp1 + j*128 + 4*lane);
        }
        if (HASREM) {
            rr0 = *(const uint32_t*)(hp0 + NFULL*128 + 2*lane);
            rr1 = *(const uint32_t*)(hp1 + NFULL*128 + 2*lane);
        }
        float ex0 = 0.f, ex1 = 0.f;
        if (lane < H) {
            float e0 = ev0 + adv; e0 = (e0 > 0.f) ? e0 : 0.2f*e0;
            float e1 = ev1 + adv; e1 = (e1 > 0.f) ? e1 : 0.2f*e1;
            ex0 = __expf(e0);
            ex1 = __expf(e1);
            den += ex0 + ex1;
        }
        #pragma unroll
        for (int j = 0; j < NFULL; j++) {
            float x0 = __shfl_sync(0xffffffffu, ex0, headF[j]);
            float x1 = __shfl_sync(0xffffffffu, ex1, headF[j]);
            float2 a0 = __half22float2(*reinterpret_cast<__half2*>(&rv0[j].x));
            float2 b0 = __half22float2(*reinterpret_cast<__half2*>(&rv0[j].y));
            float2 a1 = __half22float2(*reinterpret_cast<__half2*>(&rv1[j].x));
            float2 b1 = __half22float2(*reinterpret_cast<__half2*>(&rv1[j].y));
            accF[j].x = fmaf(x0, a0.x, fmaf(x1, a1.x, accF[j].x));
            accF[j].y = fmaf(x0, a0.y, fmaf(x1, a1.y, accF[j].y));
            accF[j].z = fmaf(x0, b0.x, fmaf(x1, b1.x, accF[j].z));
            accF[j].w = fmaf(x0, b0.y, fmaf(x1, b1.y, accF[j].w));
        }
        if (HASREM) {
            float x0 = __shfl_sync(0xffffffffu, ex0, headR);
            float x1 = __shfl_sync(0xffffffffu, ex1, headR);
            float2 r0 = __half22float2(*reinterpret_cast<__half2*>(&rr0));
            float2 r1 = __half22float2(*reinterpret_cast<__half2*>(&rr1));
            accR.x = fmaf(x0, r0.x, fmaf(x1, r1.x, accR.x));
            accR.y = fmaf(x0, r0.y, fmaf(x1, r1.y, accR.y));
        }
    }
    if (i < e) {   // tail edge
        int s = g_srcs[i];
        float ex = 0.f;
        if (lane < H) {
            float ev = as_in[s*H + lane] + adv;
            ev = (ev > 0.f) ? ev : 0.2f*ev;
            ex = __expf(ev);
            den += ex;
        }
        const __half* hp = h + (long)s*CH;
        #pragma unroll
        for (int j = 0; j < NFULL; j++) {
            uint2 rv = *(const uint2*)(hp + j*128 + 4*lane);
            float exh = __shfl_sync(0xffffffffu, ex, headF[j]);
            float2 a = __half22float2(*reinterpret_cast<__half2*>(&rv.x));
            float2 bq = __half22float2(*reinterpret_cast<__half2*>(&rv.y));
            accF[j].x = fmaf(exh, a.x, accF[j].x);
            accF[j].y = fmaf(exh, a.y, accF[j].y);
            accF[j].z = fmaf(exh, bq.x, accF[j].z);
            accF[j].w = fmaf(exh, bq.y, accF[j].w);
        }
        if (HASREM) {
            uint32_t rr = *(const uint32_t*)(hp + NFULL*128 + 2*lane);
            float exh = __shfl_sync(0xffffffffu, ex, headR);
            float2 r = __half22float2(*reinterpret_cast<__half2*>(&rr));
            accR.x = fmaf(exh, r.x, accR.x);
            accR.y = fmaf(exh, r.y, accR.y);
        }
    }

    #pragma unroll
    for (int j = 0; j < NFULL; j++) {
        float dh = __shfl_sync(0xffffffffu, den, headF[j]);
        float4 bb = *(const float4*)&bias[j*128 + 4*lane];
        float4 o;
        o.x = accF[j].x/dh + bb.x;  o.x = (o.x > 0.f) ? o.x : expm1f(o.x);
        o.y = accF[j].y/dh + bb.y;  o.y = (o.y > 0.f) ? o.y : expm1f(o.y);
        o.z = accF[j].z/dh + bb.z;  o.z = (o.z > 0.f) ? o.z : expm1f(o.z);
        o.w = accF[j].w/dh + bb.w;  o.w = (o.w > 0.f) ? o.w : expm1f(o.w);
        *(float4*)&out[(long)v*CH + j*128 + 4*lane] = o;
    }
    if (HASREM) {
        float dh = __shfl_sync(0xffffffffu, den, headR);
        float2 bb = *(const float2*)&bias[NFULL*128 + 2*lane];
        float2 o;
        o.x = accR.x/dh + bb.x;  o.x = (o.x > 0.f) ? o.x : expm1f(o.x);
        o.y = accR.y/dh + bb.y;  o.y = (o.y > 0.f) ? o.y : expm1f(o.y);
        *(float2*)&out[(long)v*CH + NFULL*128 + 2*lane] = o;
    }
}

// ---------------- pair head ----------------
__global__ void pair_kernel(const float* __restrict__ x2,
                            const int* __restrict__ n1,
                            const int* __restrict__ n2,
                            const float* __restrict__ linW,
                            const float* __restrict__ linb,
                            float* __restrict__ y, int P)
{
    int p = blockIdx.x*blockDim.x + threadIdx.x;
    if (p >= P) return;
    const float* a  = x2 + (long)n1[p]*CH2;
    const float* bb = x2 + (long)n2[p]*CH2;
    float y0 = linb[0], y1 = linb[1];
    #pragma unroll
    for (int j = 0; j < CH2; j++) {
        float v = a[j];
        y0 = fmaf(v, linW[j*2],   y0);
        y1 = fmaf(v, linW[j*2+1], y1);
    }
    #pragma unroll
    for (int j = 0; j < CH2; j++) {
        float v = bb[j];
        y0 = fmaf(v, linW[(CH2+j)*2],   y0);
        y1 = fmaf(v, linW[(CH2+j)*2+1], y1);
    }
    y[p*2]   = 1.f/(1.f + __expf(-y0));
    y[p*2+1] = 1.f/(1.f + __expf(-y1));
}

// ---------------- launch ----------------
extern "C" void kernel_launch(void* const* d_in, const int* in_sizes, int n_in,
                              void* d_out, int out_size)
{
    const float* features = (const float*)d_in[0];
    const int*   eidx     = (const int*)  d_in[1];
    const int*   n1idx    = (const int*)  d_in[2];
    const int*   n2idx    = (const int*)  d_in[3];
    const float* W1       = (const float*)d_in[4];
    const float* attS1    = (const float*)d_in[5];
    const float* attD1    = (const float*)d_in[6];
    const float* b1       = (const float*)d_in[7];
    const float* W2       = (const float*)d_in[8];
    const float* attS2    = (const float*)d_in[9];
    const float* attD2    = (const float*)d_in[10];
    const float* b2       = (const float*)d_in[11];
    const float* linW     = (const float*)d_in[12];
    const float* linb     = (const float*)d_in[13];

    const int N = N_NODES;
    const int E = in_sizes[1] / 2;
    const int P = in_sizes[2];
    const int etot = E + N;
    const int* srcE = eidx;
    const int* dstE = eidx + E;

    float* y_out  = (float*)d_out;          // [P,2]
    float* x2_out = y_out + (long)P*2;      // [N,64]

    float *p_h1, *p_x1, *p_h2, *p_as1, *p_ad1, *p_as2, *p_ad2;
    __half *p_h1h, *p_h2h;
    cudaGetSymbolAddress((void**)&p_h1,  g_h1);
    cudaGetSymbolAddress((void**)&p_h1h, g_h1h);
    cudaGetSymbolAddress((void**)&p_x1,  g_x1);
    cudaGetSymbolAddress((void**)&p_h2,  g_h2);
    cudaGetSymbolAddress((void**)&p_h2h, g_h2h);
    cudaGetSymbolAddress((void**)&p_as1, g_as1);
    cudaGetSymbolAddress((void**)&p_ad1, g_ad1);
    cudaGetSymbolAddress((void**)&p_as2, g_as2);
    cudaGetSymbolAddress((void**)&p_ad2, g_ad2);

    // ---- CSR build; gemm1 kept as 4th launch for the ncu sample ----
    zero_kernel<<<(N+255)/256, 256>>>(N);
    count_kernel<<<(etot+255)/256, 256>>>(dstE, E, N);
    int nb = (N + 1023) / 1024;
    scan1_kernel<<<nb, 1024>>>(N);
    {
        dim3 grid((N + 127)/128, CH1/96);
        gemm_tc_kernel<96><<<grid, 256>>>(features, W1, p_h1, p_h1h, N, CH1, NUM_FEA);
    }
    scan2_kernel<<<1, 64>>>(nb);
    scan3_kernel<<<(N+255)/256, 256>>>(N);
    scatter_kernel<<<(etot+255)/256, 256>>>(srcE, dstE, E, N);

    // ---- layer 1 ----
    attn_kernel<HEAD1, HID1><<<(N*HEAD1 + 255)/256, 256>>>(p_h1, attS1, attD1, p_as1, p_ad1, N);
    agg_kernel<HEAD1, HID1><<<(N*32 + 255)/256, 256>>>(p_h1h, p_as1, p_ad1, b1, p_x1, N);

    // ---- layer 2 ----
    {
        dim3 grid((N + 127)/128, 1);
        gemm_tc_kernel<64><<<grid, 256>>>(p_x1, W2, p_h2, p_h2h, N, CH2, CH1);
    }
    attn_kernel<HEAD2, HID2><<<(N*HEAD2 + 255)/256, 256>>>(p_h2, attS2, attD2, p_as2, p_ad2, N);
    agg_kernel<HEAD2, HID2><<<(N*32 + 255)/256, 256>>>(p_h2h, p_as2, p_ad2, b2, x2_out, N);

    // ---- pair head ----
    pair_kernel<<<(P+255)/256, 256>>>(x2_out, n1idx, n2idx, linW, linb, y_out, P);
}